// round 17
// baseline (speedup 1.0000x reference)
#include <cuda_runtime.h>

// SSIM loss, fused separable Gaussian convs, vertical-first, f32x2-packed
// streams (a,b) and (aa+bb, ab). 128x16 tile @ 512 threads: horizontal halo
// overhead 7.8% (was 15.6%), half the blocks, perfect stage-B task balance,
// 3 CTAs/SM x 16 warps = 48 warps (same occupancy as previous 6x8).

#define IMG     512
#define W_T     128
#define H_T     16
#define RW      138         // intermediate cols = W_T + 10
#define RH      26          // raw rows = H_T + 10
#define PAIRS   70          // float2 gmem pairs per raw row (140 cols, x-shifted)
#define STR_AB  140         // raw-tile stride in float2 units (even -> STS.128 ok)
#define STR_V   138         // sM/sS stride in float2 units (even; 276%32=20 -> LDS.128 conflict-free)
#define NT      512
#define NBLK    (4 * 32 * 64)   // 8192 blocks

// smem u64 words: 26*140 + 2*16*138 = 3640 + 4416 = 8056 -> 64448 B (3 CTAs/SM)
#define SMEM_BYTES ((RH * STR_AB + 2 * H_T * STR_V) * 8)

#define SSIM_C1 0.0001f
#define SSIM_C2 0.0009f

typedef unsigned long long u64;

__device__ float        g_part[NBLK];
__device__ unsigned int g_ctr;

__device__ __forceinline__ u64 fma2(u64 a, u64 b, u64 c) {
    u64 d; asm("fma.rn.f32x2 %0,%1,%2,%3;" : "=l"(d) : "l"(a), "l"(b), "l"(c));
    return d;
}
__device__ __forceinline__ u64 pk2(float lo, float hi) {
    u64 r; asm("mov.b64 %0,{%1,%2};" : "=l"(r) : "f"(lo), "f"(hi));
    return r;
}
__device__ __forceinline__ float2 upk(u64 v) {
    float2 f; asm("mov.b64 {%0,%1},%2;" : "=f"(f.x), "=f"(f.y) : "l"(v));
    return f;
}

// broadcast-pair tap constant (compile-time folded bit pattern)
#define TAPD(g) ((((u64)__float_as_uint(g)) << 32) | (u64)__float_as_uint(g))

__global__ __launch_bounds__(NT, 3) void ssim_main_kernel(
    const float* __restrict__ x_hat,
    const float* __restrict__ x,
    float* __restrict__ out,
    double inv_n)
{
    extern __shared__ u64 smem_u[];
    u64* sAB = smem_u;                      // [RH][STR_AB]  packed (a,b) per pixel
    u64* sM  = sAB + RH * STR_AB;           // [H_T][STR_V]  packed (mu_a, mu_b) vert
    u64* sS  = sM  + H_T * STR_V;           // [H_T][STR_V]  packed (Saa+bb, Sab) vert

    const int tid = threadIdx.x;
    const int tx0 = blockIdx.x * W_T;
    const int ty0 = blockIdx.y * H_T;
    const long imgoff = (long)blockIdx.z * (IMG * IMG);
    const float* px  = x     + imgoff;
    const float* pxh = x_hat + imgoff;

    // 6 unique symmetric taps, duplicated across both f32x2 lanes
    const u64 G2[11] = {
        TAPD(0.00102838f), TAPD(0.00759877f), TAPD(0.03600077f),
        TAPD(0.10936070f), TAPD(0.21300554f), TAPD(0.26601173f),
        TAPD(0.21300554f), TAPD(0.10936070f), TAPD(0.03600077f),
        TAPD(0.00759877f), TAPD(0.00102838f)
    };

    // ---- Stage 1: float2 gmem loads, transform, interleave (a,b), zero-pad ----
    // smem col 0 = pixel x (tx0-6); pairs even-aligned so each pair is fully
    // inside or fully outside the image row.
    for (int i = tid; i < RH * PAIRS; i += NT) {
        int r = i / PAIRS;
        int c = i - r * PAIRS;
        int gy = ty0 + r - 5;
        int gx = tx0 - 6 + 2 * c;
        float4 w = make_float4(0.f, 0.f, 0.f, 0.f);
        if ((unsigned)gy < IMG && (unsigned)gx < IMG) {
            const float2 vx = *(const float2*)(px  + (long)gy * IMG + gx);
            const float2 vh = *(const float2*)(pxh + (long)gy * IMG + gx);
            w.x = fmaf(0.5f, vx.x, 0.5f);   // a, pixel gx
            w.y = fmaf(0.5f, vh.x, 0.5f);   // b, pixel gx
            w.z = fmaf(0.5f, vx.y, 0.5f);   // a, pixel gx+1
            w.w = fmaf(0.5f, vh.y, 0.5f);   // b, pixel gx+1
        }
        *(float4*)(sAB + r * STR_AB + 2 * c) = w;
    }
    __syncthreads();

    // ---- Stage A: VERTICAL 11-tap conv, 2 packed streams ----
    // 552 tasks = 4 y-segments (4 outputs) x RW cols.
    for (int t = tid; t < 4 * RW; t += NT) {
        int seg = t / RW;
        int col = t - seg * RW;
        int y0  = seg * 4;
        const u64* pc = sAB + y0 * STR_AB + (col + 1);

        u64 accM[4] = {0, 0, 0, 0};
        u64 accS[4] = {0, 0, 0, 0};

        #pragma unroll
        for (int j = 0; j < 14; j++) {
            u64 vab = pc[j * STR_AB];
            float2 f = upk(vab);
            float ss = fmaf(f.y, f.y, f.x * f.x);   // aa + bb
            float ab = f.x * f.y;
            u64 vsp = pk2(ss, ab);
            #pragma unroll
            for (int o = 0; o < 4; o++) {
                int k = j - o;
                if (k >= 0 && k < 11) {
                    accM[o] = fma2(G2[k], vab, accM[o]);
                    accS[o] = fma2(G2[k], vsp, accS[o]);
                }
            }
        }
        #pragma unroll
        for (int o = 0; o < 4; o++) {
            sM[(y0 + o) * STR_V + col] = accM[o];
            sS[(y0 + o) * STR_V + col] = accS[o];
        }
    }
    __syncthreads();

    // ---- Stage B: HORIZONTAL 11-tap conv (LDS.128 pairs) + SSIM combine ----
    // 512 tasks = 16 rows x 32 col-segments (4 outputs each), exactly 1/thread.
    float lsum = 0.0f;
    {
        const int row = tid & (H_T - 1);
        const int cb  = (tid >> 4) * 4;     // 0..124
        const ulonglong2* pM = (const ulonglong2*)(sM + row * STR_V + cb);
        const ulonglong2* pS = (const ulonglong2*)(sS + row * STR_V + cb);

        u64 accM[4] = {0, 0, 0, 0};
        u64 accS[4] = {0, 0, 0, 0};

        #pragma unroll
        for (int q = 0; q < 7; q++) {       // 14 window cols as 7 LDS.128 per plane
            ulonglong2 m2 = pM[q];
            ulonglong2 s2 = pS[q];
            #pragma unroll
            for (int e = 0; e < 2; e++) {
                int jj = 2 * q + e;
                u64 vm = e ? m2.y : m2.x;
                u64 vs = e ? s2.y : s2.x;
                #pragma unroll
                for (int o = 0; o < 4; o++) {
                    int k = jj - o;
                    if (k >= 0 && k < 11) {
                        accM[o] = fma2(G2[k], vm, accM[o]);
                        accS[o] = fma2(G2[k], vs, accS[o]);
                    }
                }
            }
        }
        #pragma unroll
        for (int o = 0; o < 4; o++) {
            float2 M = upk(accM[o]);        // (mu_x, mu_y)
            float2 S = upk(accS[o]);        // (E[aa+bb], E[ab])
            float mux = M.x, muy = M.y;
            float mux2 = mux * mux;
            float muy2 = muy * muy;
            float muxy = mux * muy;
            float sxy  = S.y - muxy;
            float sxsy = S.x - mux2 - muy2;
            float num = (2.0f * muxy + SSIM_C1) * (2.0f * sxy + SSIM_C2);
            float den = (mux2 + muy2 + SSIM_C1) * (sxsy + SSIM_C2);
            lsum += __fdividef(num, den + 1e-8f);
        }
    }

    // ---- Stage 4: block reduce, publish partial, last block finalizes ----
    #pragma unroll
    for (int off = 16; off > 0; off >>= 1)
        lsum += __shfl_xor_sync(0xffffffffu, lsum, off);

    __syncthreads();
    float* wpart = (float*)smem_u;    // reuse
    if ((tid & 31) == 0) wpart[tid >> 5] = lsum;
    __syncthreads();

    __shared__ unsigned int s_rank;
    if (tid == 0) {
        float s = 0.0f;
        #pragma unroll
        for (int w = 0; w < NT / 32; w++) s += wpart[w];
        int blin = (blockIdx.z * gridDim.y + blockIdx.y) * gridDim.x + blockIdx.x;
        g_part[blin] = s;
        __threadfence();
        s_rank = atomicAdd(&g_ctr, 1u);
    }
    __syncthreads();

    if (s_rank == NBLK - 1) {         // last block finalizes
        __threadfence();
        double d = 0.0;
        for (int i = tid; i < NBLK; i += NT) d += (double)g_part[i];
        #pragma unroll
        for (int off = 16; off > 0; off >>= 1)
            d += __shfl_xor_sync(0xffffffffu, d, off);
        __syncthreads();
        double* dpart = (double*)smem_u;
        if ((tid & 31) == 0) dpart[tid >> 5] = d;
        __syncthreads();
        if (tid == 0) {
            double s = 0.0;
            #pragma unroll
            for (int w = 0; w < NT / 32; w++) s += dpart[w];
            out[0] = (float)(1.0 - s * inv_n);
            g_ctr = 0;                // reset for next graph replay
        }
    }
}

extern "C" void kernel_launch(void* const* d_in, const int* in_sizes, int n_in,
                              void* d_out, int out_size)
{
    const float* x_hat = (const float*)d_in[0];
    const float* x     = (const float*)d_in[1];
    float* out = (float*)d_out;

    int batch = in_sizes[0] / (IMG * IMG);   // 64

    cudaFuncSetAttribute(ssim_main_kernel,
                         cudaFuncAttributeMaxDynamicSharedMemorySize, SMEM_BYTES);

    dim3 grid(IMG / W_T, IMG / H_T, batch);
    double inv_n = 1.0 / ((double)batch * IMG * IMG);
    ssim_main_kernel<<<grid, NT, SMEM_BYTES>>>(x_hat, x, out, inv_n);
}